// round 15
// baseline (speedup 1.0000x reference)
#include <cuda_runtime.h>
#include <cuda_bf16.h>
#include <math.h>
#include <float.h>
#include <stdint.h>

#define NB    8192
#define ENCD  256
#define NCL   32
#define KSEL  25
#define KEEP  26
#define BM    64          // rows per CTA tile
#define BN    64          // cols per tile
#define NBLK  128         // row blocks
#define NTHR  256
#define NCTA  148         // CTAs for main kernel (one per SM)
#define FB64  4160        // flat base of block 64 (= 64*65)
#define FLATS 8256        // total tile units (64*65 + 64*64)

// ---------------- device scratch ----------------
__device__ float    g_sq[NB];
__device__ float    g_maxp[NB];
__device__ int      g_cid[NB];
__device__ uint32_t g_loc[(size_t)3 * NB * KEEP];   // [slot][row][26] partial top-26
// Stored off-diagonal tiles: slot = bi*64 + (t-1); layout [slot][col][row], u32 packed.
__device__ uint32_t g_tile[(size_t)NBLK * 64 * 4096];   // 128 MB
// Per-strip minima: g_smin[row][p] = min packed value of strip p for that row.
__device__ uint32_t g_smin[(size_t)NB * 64];            // 2 MB
// Pre-swizzled bf16 blobs: per 32-row block jb, 32KB = [hi 16KB | lo 16KB],
// row stride 512B, per-row 16B-chunk XOR swizzle (c ^ (r&7)).
__device__ uint32_t g_Bblk[NB * 256];              // 8 MB

// ---------------- helpers ----------------
__device__ __forceinline__ uint32_t smem_to_u32(const void* p) {
    uint32_t a;
    asm("{ .reg .u64 t; cvta.to.shared.u64 t, %1; cvt.u32.u64 %0, t; }" : "=r"(a) : "l"(p));
    return a;
}
__device__ __forceinline__ void cp16(uint32_t s, const void* g) {
    asm volatile("cp.async.cg.shared.global [%0], [%1], 16;" :: "r"(s), "l"(g) : "memory");
}
__device__ __forceinline__ void cp_commit() {
    asm volatile("cp.async.commit_group;" ::: "memory");
}
template <int N>
__device__ __forceinline__ void cp_wait() {
    asm volatile("cp.async.wait_group %0;" :: "n"(N) : "memory");
}
#define LDSM4(r0, r1, r2, r3, addr) \
    asm volatile("ldmatrix.sync.aligned.m8n8.x4.shared.b16 {%0,%1,%2,%3}, [%4];" \
                 : "=r"(r0), "=r"(r1), "=r"(r2), "=r"(r3) : "r"(addr))
#define MMA16816(d, a0, a1, a2, a3, b0, b1) \
    asm volatile("mma.sync.aligned.m16n8k16.row.col.f32.bf16.bf16.f32 " \
                 "{%0,%1,%2,%3}, {%4,%5,%6,%7}, {%8,%9}, {%0,%1,%2,%3};" \
                 : "+f"((d)[0]), "+f"((d)[1]), "+f"((d)[2]), "+f"((d)[3]) \
                 : "r"(a0), "r"(a1), "r"(a2), "r"(a3), "r"(b0), "r"(b1))

// ---------------- smem layout (bytes) ----------------
#define SM_A      0        // 64KB: A hi [64][512B], then A lo at +32768
#define SM_B      65536    // 3 x 32KB chunk bufs ([hi 16KB | lo 16KB], row stride 256B)
#define SM_CAND   163840   // 64 rows x 64 cap x 4B local candidate stacks
#define SM_RV     180224   // 64 x 26 f32 packed top-lists
#define SM_SQA    186880   // 64 f32
#define SM_SQB    187136   // 64 f32
#define SM_CIDB   187392   // 64 int
#define SM_THR    187648   // 64 f32 (packed, local rows)
#define SM_CN     187904   // 64 int
#define SM_CIDA   188160   // 64 int (cid of own rows)
#define SM_STAGE  188416   // 16KB tile staging [col][row] u32
#define SM_COLMIN 204800   // 2 x 64 f32 per-warp-half column minima
#define SMEM_BYTES 205312

// ---------------------------------------------------------------------------
// prep1: row sum-of-squares; argmax/max of categorical; g_loc sentinel fill.
// ---------------------------------------------------------------------------
__global__ void prep_kernel(const float* __restrict__ enc,
                            const float* __restrict__ cat) {
    int warp = (blockIdx.x * blockDim.x + threadIdx.x) >> 5;
    int lane = threadIdx.x & 31;
    if (warp >= NB) return;

    const float* e = enc + (size_t)warp * ENCD;
    float s = 0.f;
#pragma unroll
    for (int i = 0; i < ENCD / 32; ++i) { float v = e[lane + 32 * i]; s += v * v; }
#pragma unroll
    for (int off = 16; off; off >>= 1) s += __shfl_xor_sync(0xffffffffu, s, off);

    float v = cat[(size_t)warp * NCL + lane];
    int idx = lane;
#pragma unroll
    for (int off = 16; off; off >>= 1) {
        float ov = __shfl_xor_sync(0xffffffffu, v, off);
        int   oi = __shfl_xor_sync(0xffffffffu, idx, off);
        if (ov > v || (ov == v && oi < idx)) { v = ov; idx = oi; }
    }
    if (lane == 0) { g_sq[warp] = s; g_maxp[warp] = v; g_cid[warp] = idx; }

    // sentinel-fill all 3 partial-list slots (FLT_MAX bits)
    for (int i = lane; i < 3 * KEEP; i += 32)
        g_loc[((size_t)(i / KEEP) * NB + warp) * KEEP + (i % KEEP)] = 0x7F7FFFFFu;
}

// ---------------------------------------------------------------------------
// prep2: bf16 hi/lo split into pre-swizzled 32-row blobs.
// ---------------------------------------------------------------------------
__global__ void prep_b_kernel(const float* __restrict__ E) {
    int gid = blockIdx.x * blockDim.x + threadIdx.x;   // NB*32 threads
    int jb = gid >> 10;
    int r  = (gid >> 5) & 31;
    int c  = gid & 31;

    const float* src = E + (size_t)(jb * 32 + r) * ENCD + c * 8;
    float4 v0 = *(const float4*)src;
    float4 v1 = *(const float4*)(src + 4);
    float f[8] = {v0.x, v0.y, v0.z, v0.w, v1.x, v1.y, v1.z, v1.w};

    uint32_t hi[4], lo[4];
#pragma unroll
    for (int i = 0; i < 4; ++i) {
        __nv_bfloat16 h0 = __float2bfloat16(f[2 * i]);
        __nv_bfloat16 h1 = __float2bfloat16(f[2 * i + 1]);
        __nv_bfloat16 l0 = __float2bfloat16(f[2 * i] - __bfloat162float(h0));
        __nv_bfloat16 l1 = __float2bfloat16(f[2 * i + 1] - __bfloat162float(h1));
        __nv_bfloat162 hp; hp.x = h0; hp.y = h1;
        __nv_bfloat162 lp; lp.x = l0; lp.y = l1;
        hi[i] = *(uint32_t*)&hp;
        lo[i] = *(uint32_t*)&lp;
    }

    int base = jb * 8192;                                   // u32 units (32KB blob)
    int off  = (r * 512 + ((c ^ (r & 7)) << 4)) >> 2;       // u32 units
    *(uint4*)(g_Bblk + base + off)        = make_uint4(hi[0], hi[1], hi[2], hi[3]);
    *(uint4*)(g_Bblk + base + 4096 + off) = make_uint4(lo[0], lo[1], lo[2], lo[3]);
}

// ---------------------------------------------------------------------------
// Kernel A: 148 CTAs, persistent over a contiguous range of the flattened
// symmetric tile list (8256 units). Range spans <=2 row-blocks -> <=2
// segments, each with its own A prologue + selection state, writing a
// partial top-26 list to its slot. Per-chunk math FROZEN (bf16 3-term,
// f32 acc); triple-buffered B ring, early prefetch.
// ---------------------------------------------------------------------------
__global__ void __launch_bounds__(NTHR, 1)
hmma_main() {
    extern __shared__ char smem[];
    const uint32_t sb = smem_to_u32(smem);
    const int tid  = threadIdx.x;
    const int lane = tid & 31;
    const int wid  = tid >> 5;
    const int mw   = wid & 1;        // 0/1 -> rows mw*32..+32
    const int nw   = wid >> 1;       // 0..3 -> cols nw*16..+16

    float* s_sqa  = (float*)(smem + SM_SQA);
    float* s_sqb  = (float*)(smem + SM_SQB);
    int*   s_cidb = (int*)(smem + SM_CIDB);
    float* s_thr  = (float*)(smem + SM_THR);
    int*   s_cn   = (int*)(smem + SM_CN);
    int*   s_cida = (int*)(smem + SM_CIDA);
    uint32_t* s_cand  = (uint32_t*)(smem + SM_CAND);
    uint32_t* s_stage = (uint32_t*)(smem + SM_STAGE);
    float* s_colmin = (float*)(smem + SM_COLMIN);   // [2][64]
    float* s_rv   = (float*)(smem + SM_RV);

    // ---- per-lane ldmatrix addressing (segment-invariant) ----
    const int lr = lane & 7, gq = lane >> 3;
    int a_row0 = mw * 32 + ((gq & 1) << 3) + lr;
    int a_row1 = a_row0 + 16;
    const uint32_t a_base0 = sb + SM_A + a_row0 * 512;
    const uint32_t a_base1 = sb + SM_A + a_row1 * 512;
    const int a_sw0 = a_row0 & 7, a_sw1 = a_row1 & 7;
    const int a_cb  = gq >> 1;
    const int j_l  = nw * 16 + ((gq >> 1) << 3) + lr;
    const int b_sw = j_l & 7;
    const int b_cb = gq & 1;
    const uint32_t b_roff = j_l * 256;
    const int q  = lane >> 2;
    const int e0 = (lane & 3) * 2;

    const int c = blockIdx.x;
    int sflat = (int)(((long long)c * FLATS) / NCTA);
    const int eflat = (int)(((long long)(c + 1) * FLATS) / NCTA);

    while (sflat < eflat) {
        // ---- derive segment: block bi, tiles [t0, t1) ----
        int bi, t0;
        if (sflat < FB64) { bi = sflat / 65; t0 = sflat - bi * 65; }
        else { int g = sflat - FB64; bi = 64 + (g >> 6); t0 = g & 63; }
        const int fb   = (bi < 64) ? bi * 65 : FB64 + ((bi - 64) << 6);
        const int blen = (bi < 64) ? 65 : 64;
        int segend = fb + blen; if (segend > eflat) segend = eflat;
        const int nchunk = (segend - sflat) * 2;
        const int slot = c - (int)((((long long)fb + 1) * NCTA - 1) / FLATS);
        const int row0 = bi * BM;
        const int b2   = bi * 2;

        cp_wait<0>();
        __syncthreads();   // prior segment fully done before overwriting A/B/state

        // ---- segment prologue: A (64KB) + chunk(t0,h0); chunk(t0,h1) ----
        {
            const int bj0 = (bi + t0) & (NBLK - 1);
#pragma unroll
            for (int i = 0; i < 16; ++i) {
                int ck = tid + i * 256;                 // 0..4095 16B pieces
                int p  = ck >> 10;
                int off = ck & 1023;
                const uint32_t* src = g_Bblk + (size_t)(b2 + (p >> 1)) * 8192
                                             + (size_t)(p & 1) * 4096 + off * 4;
                cp16(sb + SM_A + (uint32_t)(p & 1) * 32768u + (uint32_t)(p >> 1) * 16384u + off * 16, src);
            }
#pragma unroll
            for (int i = 0; i < 8; ++i) {
                int ci = tid + i * 256;
                int hilo = ci >> 10, j = (ci >> 4) & 63, cc2 = ci & 15;
                const uint32_t* src = g_Bblk + (size_t)(2 * bj0 + (j >> 5)) * 8192
                                             + (size_t)hilo * 4096 + (j & 31) * 128 + cc2 * 4;
                cp16(sb + SM_B + hilo * 16384u + j * 256u + cc2 * 16u, src);
            }
            cp_commit();   // group: A + chunk(t0,0)
#pragma unroll
            for (int i = 0; i < 8; ++i) {
                int ci = tid + i * 256;
                int hilo = ci >> 10, j = (ci >> 4) & 63, cc2 = ci & 15;
                const uint32_t* src = g_Bblk + (size_t)(2 * bj0 + (j >> 5)) * 8192
                                             + (size_t)hilo * 4096 + (j & 31) * 128 + 64 + cc2 * 4;
                cp16(sb + SM_B + 32768u + hilo * 16384u + j * 256u + cc2 * 16u, src);
            }
            cp_commit();   // group: chunk(t0,1)
        }

        if (tid < BM) {
            s_sqa[tid]  = g_sq[row0 + tid];
            s_cida[tid] = g_cid[row0 + tid];
            s_thr[tid]  = FLT_MAX;
            s_cn[tid]   = 0;
        }

        int mcnt = 0;
        float acc[2][2][4];
        int buf = 0;

#pragma unroll 1
        for (int gc = 0; gc < nchunk; ++gc) {
            const int t = t0 + (gc >> 1), h = gc & 1;
            const int bj = (bi + t) & (NBLK - 1);
            const uint32_t Bb = sb + SM_B + (uint32_t)buf * 32768u;

            cp_wait<1>();
            __syncthreads();   // chunk gc visible; all warps done with chunk gc-1

            if (h == 0) {
#pragma unroll
                for (int ms = 0; ms < 2; ++ms)
#pragma unroll
                    for (int ns = 0; ns < 2; ++ns)
#pragma unroll
                        for (int cc2 = 0; cc2 < 4; ++cc2) acc[ms][ns][cc2] = 0.f;
            } else if (tid < BN) {
                int j = bj * BN + tid;
                s_sqb[tid]  = g_sq[j];
                s_cidb[tid] = g_cid[j];
            }

            // ---- prefetch chunk gc+2 into the buffer freed at gc-1 ----
            {
                int pbuf = buf + 2; if (pbuf >= 3) pbuf -= 3;
                if (gc + 2 < nchunk) {
                    const int t2 = t0 + ((gc + 2) >> 1), h2 = (gc + 2) & 1;
                    const int bj2 = (bi + t2) & (NBLK - 1);
                    const uint32_t dstB = sb + SM_B + (uint32_t)pbuf * 32768u;
#pragma unroll
                    for (int i = 0; i < 8; ++i) {
                        int ci = tid + i * 256;
                        int hilo = ci >> 10, j = (ci >> 4) & 63, cc2 = ci & 15;
                        const uint32_t* src = g_Bblk + (size_t)(2 * bj2 + (j >> 5)) * 8192
                                                     + (size_t)hilo * 4096 + (j & 31) * 128
                                                     + h2 * 64 + cc2 * 4;
                        cp16(dstB + hilo * 16384u + j * 256u + cc2 * 16u, src);
                    }
                }
                cp_commit();
            }

            // ---- compute chunk: 8 ksteps x (6 LDSM4 + 12 MMA) [FROZEN] ----
            const uint32_t aho = (uint32_t)h * 256u;
#pragma unroll
            for (int s = 0; s < 8; ++s) {
                const int kc = s * 2;
                uint32_t ah0[4], ah1[4], al0[4], al1[4], bh[4], bl[4];
                LDSM4(ah0[0], ah0[1], ah0[2], ah0[3], a_base0 + aho + (uint32_t)(((kc + a_cb) ^ a_sw0) << 4));
                LDSM4(ah1[0], ah1[1], ah1[2], ah1[3], a_base1 + aho + (uint32_t)(((kc + a_cb) ^ a_sw1) << 4));
                LDSM4(bh[0], bh[1], bh[2], bh[3], Bb + b_roff + (uint32_t)(((kc + b_cb) ^ b_sw) << 4));
                LDSM4(bl[0], bl[1], bl[2], bl[3], Bb + 16384u + b_roff + (uint32_t)(((kc + b_cb) ^ b_sw) << 4));
                LDSM4(al0[0], al0[1], al0[2], al0[3], a_base0 + 32768u + aho + (uint32_t)(((kc + a_cb) ^ a_sw0) << 4));
                LDSM4(al1[0], al1[1], al1[2], al1[3], a_base1 + 32768u + aho + (uint32_t)(((kc + a_cb) ^ a_sw1) << 4));

                MMA16816(acc[0][0], ah0[0], ah0[1], ah0[2], ah0[3], bh[0], bh[1]);  // hi*hi
                MMA16816(acc[0][1], ah0[0], ah0[1], ah0[2], ah0[3], bh[2], bh[3]);
                MMA16816(acc[1][0], ah1[0], ah1[1], ah1[2], ah1[3], bh[0], bh[1]);
                MMA16816(acc[1][1], ah1[0], ah1[1], ah1[2], ah1[3], bh[2], bh[3]);
                MMA16816(acc[0][0], ah0[0], ah0[1], ah0[2], ah0[3], bl[0], bl[1]);  // hi*lo
                MMA16816(acc[0][1], ah0[0], ah0[1], ah0[2], ah0[3], bl[2], bl[3]);
                MMA16816(acc[1][0], ah1[0], ah1[1], ah1[2], ah1[3], bl[0], bl[1]);
                MMA16816(acc[1][1], ah1[0], ah1[1], ah1[2], ah1[3], bl[2], bl[3]);
                MMA16816(acc[0][0], al0[0], al0[1], al0[2], al0[3], bh[0], bh[1]);  // lo*hi
                MMA16816(acc[0][1], al0[0], al0[1], al0[2], al0[3], bh[2], bh[3]);
                MMA16816(acc[1][0], al1[0], al1[1], al1[2], al1[3], bh[0], bh[1]);
                MMA16816(acc[1][1], al1[0], al1[1], al1[2], al1[3], bh[2], bh[3]);
            }

            if (h == 1) {
                const bool do_store = (t != 0);
                {
                    float cm[2][2] = {{FLT_MAX, FLT_MAX}, {FLT_MAX, FLT_MAX}};
                    // ---- fused epilogue: selection + stage tile + col mins ----
#pragma unroll
                    for (int ms = 0; ms < 2; ++ms) {
#pragma unroll
                        for (int ro = 0; ro < 2; ++ro) {
                            const int row = mw * 32 + ms * 16 + ro * 8 + q;
                            const float sqa = s_sqa[row];
                            const float thr = s_thr[row];
                            const uint32_t cida = (uint32_t)s_cida[row];
#pragma unroll
                            for (int ns = 0; ns < 2; ++ns) {
#pragma unroll
                                for (int e = 0; e < 2; ++e) {
                                    const int col = nw * 16 + ns * 8 + e0 + e;
                                    float dot = acc[ms][ns][ro * 2 + e];
                                    float d2 = fmaxf(sqa + s_sqb[col] - 2.f * dot, 0.f);
                                    uint32_t bits = __float_as_uint(d2) & 0xFFFFFFE0u;
                                    uint32_t pk = bits | (uint32_t)s_cidb[col];
                                    if (__uint_as_float(pk) < thr) {
                                        int pos = atomicAdd(&s_cn[row], 1);
                                        s_cand[row * 64 + pos] = pk;
                                    }
                                    uint32_t sv = bits | cida;
                                    s_stage[col * 64 + row] = sv;
                                    cm[ns][e] = fminf(cm[ns][e], __uint_as_float(sv));
                                }
                            }
                        }
                    }
                    // reduce col mins across the 8 q-lanes
#pragma unroll
                    for (int ns = 0; ns < 2; ++ns)
#pragma unroll
                        for (int e = 0; e < 2; ++e) {
                            float m = cm[ns][e];
                            m = fminf(m, __shfl_xor_sync(0xffffffffu, m, 4));
                            m = fminf(m, __shfl_xor_sync(0xffffffffu, m, 8));
                            m = fminf(m, __shfl_xor_sync(0xffffffffu, m, 16));
                            if (lane < 4)
                                s_colmin[mw * 64 + nw * 16 + ns * 8 + lane * 2 + e] = m;
                        }
                }
                __syncthreads();   // epilogue writes visible to maintainers

                // ---- maintainers: merge candidates into sorted top-26 ----
                if (tid < BM) {
                    int n = s_cn[tid];
                    float* rv = s_rv + tid * KEEP;
                    for (int i = 0; i < n; ++i) {
                        float v = __uint_as_float(s_cand[tid * 64 + i]);
                        if (mcnt < KEEP) {
                            int p = mcnt++;
                            while (p > 0 && rv[p - 1] > v) { rv[p] = rv[p - 1]; --p; }
                            rv[p] = v;
                        } else if (v < rv[KEEP - 1]) {
                            int p = KEEP - 1;
                            while (p > 0 && rv[p - 1] > v) { rv[p] = rv[p - 1]; --p; }
                            rv[p] = v;
                        }
                    }
                    s_thr[tid] = (mcnt == KEEP) ? rv[KEEP - 1] : FLT_MAX;
                    s_cn[tid] = 0;
                    // strip min for receiving row (bj*64+tid) at p = t-1
                    if (do_store) {
                        float mnn = fminf(s_colmin[tid], s_colmin[64 + tid]);
                        g_smin[(size_t)(bj * 64 + tid) * 64 + (t - 1)] = __float_as_uint(mnn);
                    }
                }

                // ---- coalesced copy of staged tile to global ----
                if (do_store) {
                    uint4* dst = (uint4*)(g_tile + (size_t)(bi * 64 + (t - 1)) * 4096);
                    const uint4* s4 = (const uint4*)s_stage;
#pragma unroll
                    for (int i = 0; i < 4; ++i) dst[tid + i * 256] = s4[tid + i * 256];
                }
                // no trailing sync: next loop-top / segment-top barrier covers reuse
            }

            if (++buf == 3) buf = 0;
        }

        // ---- write this segment's partial top-26 to its slot ----
        if (tid < BM) {
            const float* rv = s_rv + tid * KEEP;
#pragma unroll
            for (int i = 0; i < KEEP; ++i)
                g_loc[((size_t)slot * NB + row0 + tid) * KEEP + i] = __float_as_uint(rv[i]);
        }

        sflat = segend;
    }
}

// ---------------------------------------------------------------------------
// Kernel B: one warp per row. Distributed sorted top-26 (lane L = rank L)
// initialized from slot 0, merged with slots 1-2, then strip sweep with
// dynamic re-filtering (lossless). Warp-parallel entropy via match_any.
// ---------------------------------------------------------------------------
__device__ __forceinline__ void dk_insert(float& mvd, float& thr, int lane, float val) {
    unsigned pb = __ballot_sync(0xffffffffu, mvd > val);
    int pos = __ffs(pb) - 1;
    float prev = __shfl_up_sync(0xffffffffu, mvd, 1);
    mvd = (lane > pos) ? prev : ((lane == pos) ? val : mvd);
    thr = __shfl_sync(0xffffffffu, mvd, KEEP - 1);
}

__device__ __forceinline__ void dk_pop(float& mvd, float& thr, int lane,
                                       float f, unsigned b) {
    while (b) {
        int sl = __ffs(b) - 1; b &= b - 1;
        float val = __shfl_sync(0xffffffffu, f, sl);
        if (val < thr) dk_insert(mvd, thr, lane, val);
    }
}

__global__ void __launch_bounds__(256)
gather_kernel(float* __restrict__ out) {
    const int w    = (blockIdx.x * blockDim.x + threadIdx.x) >> 5;   // row
    const int lane = threadIdx.x & 31;
    if (w >= NB) return;
    const int bj = w >> 6, cl = w & 63;

    // init from slot 0, merge slots 1-2 (sentinel FLT_MAX if unused)
    float mvd = (lane < KEEP) ? __uint_as_float(g_loc[(size_t)w * KEEP + lane])
                              : FLT_MAX;
    float thr = __shfl_sync(0xffffffffu, mvd, KEEP - 1);
#pragma unroll
    for (int slot = 1; slot < 3; ++slot) {
        float f = (lane < KEEP)
                ? __uint_as_float(g_loc[((size_t)slot * NB + w) * KEEP + lane])
                : FLT_MAX;
        unsigned hb = __ballot_sync(0xffffffffu, f < thr);
        if (hb) dk_pop(mvd, thr, lane, f, hb);
    }

    const uint32_t* minb = g_smin + (size_t)w * 64;
    float m0 = __uint_as_float(__ldg(minb + lane));
    float m1 = __uint_as_float(__ldg(minb + lane + 32));
    unsigned b0 = __ballot_sync(0xffffffffu, m0 < thr);
    unsigned b1 = __ballot_sync(0xffffffffu, m1 < thr);
    unsigned long long mask = ((unsigned long long)b1 << 32) | (unsigned long long)b0;
    if (bj < 64) mask &= 0x7FFFFFFFFFFFFFFFull;   // p=63 invalid (never written)

    while (mask) {
        int pa[4]; uint2 v[4];
        int cnt = 0;
#pragma unroll
        for (int u = 0; u < 4; ++u) {
            if (mask) {
                pa[cnt] = __ffsll((long long)mask) - 1;
                mask &= mask - 1;
                ++cnt;
            }
        }
#pragma unroll
        for (int u = 0; u < 4; ++u) {
            if (u < cnt) {
                const int p = pa[u];
                const int bi = (bj - (p + 1)) & (NBLK - 1);
                v[u] = __ldg((const uint2*)(g_tile + (size_t)(bi * 64 + p) * 4096
                                            + cl * 64 + lane * 2));
            }
        }
#pragma unroll
        for (int u = 0; u < 4; ++u) {
            if (u < cnt) {
                float f0 = __uint_as_float(v[u].x), f1 = __uint_as_float(v[u].y);
                unsigned h0 = __ballot_sync(0xffffffffu, f0 < thr);
                unsigned h1 = __ballot_sync(0xffffffffu, f1 < thr);
                if (h0) dk_pop(mvd, thr, lane, f0, h0);
                if (h1) dk_pop(mvd, thr, lane, f1, h1);
            }
        }
        if (mask) {
            unsigned nb0 = __ballot_sync(0xffffffffu, m0 < thr);
            unsigned nb1 = __ballot_sync(0xffffffffu, m1 < thr);
            mask &= ((unsigned long long)nb1 << 32) | (unsigned long long)nb0;
        }
    }

    // ---- warp-parallel entropy over the distributed list ----
    float t25 = thr;
    unsigned below = __ballot_sync(0xffffffffu, mvd < t25) & ((1u << KSEL) - 1u);
    int n = __popc(below);
    float ent = 0.f;
    if (lane < n) {
        unsigned active = (1u << n) - 1u;
        int cidL = (int)(__float_as_uint(mvd) & 31u);
        unsigned peers = __match_any_sync(active, cidL);
        if (lane == (__ffs(peers) - 1)) {
            float bins = (float)__popc(peers) / (float)n;
            ent = -bins * logf(bins + 1e-5f);
        }
    }
#pragma unroll
    for (int off = 16; off; off >>= 1)
        ent += __shfl_xor_sync(0xffffffffu, ent, off);

    if (lane == 0) out[w] = ent * g_maxp[w];
}

// ---------------------------------------------------------------------------
extern "C" void kernel_launch(void* const* d_in, const int* in_sizes, int n_in,
                              void* d_out, int out_size) {
    const float* enc = (const float*)d_in[0];
    const float* cat = (const float*)d_in[1];
    float* out = (float*)d_out;

    cudaFuncSetAttribute(hmma_main,
                         cudaFuncAttributeMaxDynamicSharedMemorySize, SMEM_BYTES);

    prep_kernel<<<NB * 32 / NTHR, NTHR>>>(enc, cat);
    prep_b_kernel<<<NB * 32 / NTHR, NTHR>>>(enc);
    hmma_main<<<NCTA, NTHR, SMEM_BYTES>>>();
    gather_kernel<<<NB * 32 / 256, 256>>>(out);
}

// round 16
// speedup vs baseline: 1.2032x; 1.2032x over previous
#include <cuda_runtime.h>
#include <cuda_bf16.h>
#include <math.h>
#include <float.h>
#include <stdint.h>

#define NB    8192
#define ENCD  256
#define NCL   32
#define KSEL  25
#define KEEP  26
#define BM    64          // rows per CTA
#define BN    64          // cols per tile
#define NBLK  128         // row blocks
#define NTILE 65          // tiles per CTA (t = 0..64)
#define NCHUNK (NTILE * 2)
#define NTHR  256

// ---------------- device scratch ----------------
__device__ float    g_sq[NB];
__device__ float    g_maxp[NB];
__device__ int      g_cid[NB];
__device__ uint32_t g_loc[NB * KEEP];              // owners' final local top-26 (packed)
// Stored off-diagonal tiles: slot = bi*64 + (t-1); layout [slot][col][row], u32 packed.
__device__ uint32_t g_tile[(size_t)NBLK * 64 * 4096];   // 128 MB
// Per-strip minima: g_smin[row][p] = min packed value of strip p for that row.
__device__ uint32_t g_smin[(size_t)NB * 64];            // 2 MB
// Pre-swizzled bf16 blobs: per 32-row block jb, 32KB = [hi 16KB | lo 16KB],
// row stride 512B, per-row 16B-chunk XOR swizzle (c ^ (r&7)).
__device__ uint32_t g_Bblk[NB * 256];              // 8 MB

// ---------------- helpers ----------------
__device__ __forceinline__ uint32_t smem_to_u32(const void* p) {
    uint32_t a;
    asm("{ .reg .u64 t; cvta.to.shared.u64 t, %1; cvt.u32.u64 %0, t; }" : "=r"(a) : "l"(p));
    return a;
}
__device__ __forceinline__ void cp16(uint32_t s, const void* g) {
    asm volatile("cp.async.cg.shared.global [%0], [%1], 16;" :: "r"(s), "l"(g) : "memory");
}
__device__ __forceinline__ void cp_commit() {
    asm volatile("cp.async.commit_group;" ::: "memory");
}
template <int N>
__device__ __forceinline__ void cp_wait() {
    asm volatile("cp.async.wait_group %0;" :: "n"(N) : "memory");
}
#define LDSM4(r0, r1, r2, r3, addr) \
    asm volatile("ldmatrix.sync.aligned.m8n8.x4.shared.b16 {%0,%1,%2,%3}, [%4];" \
                 : "=r"(r0), "=r"(r1), "=r"(r2), "=r"(r3) : "r"(addr))
#define MMA16816(d, a0, a1, a2, a3, b0, b1) \
    asm volatile("mma.sync.aligned.m16n8k16.row.col.f32.bf16.bf16.f32 " \
                 "{%0,%1,%2,%3}, {%4,%5,%6,%7}, {%8,%9}, {%0,%1,%2,%3};" \
                 : "+f"((d)[0]), "+f"((d)[1]), "+f"((d)[2]), "+f"((d)[3]) \
                 : "r"(a0), "r"(a1), "r"(a2), "r"(a3), "r"(b0), "r"(b1))

// ---------------- smem layout (bytes) ----------------
#define SM_A      0        // 64KB: A hi [64][512B], then A lo at +32768
#define SM_B      65536    // 3 x 32KB chunk bufs ([hi 16KB | lo 16KB], row stride 256B)
#define SM_CAND   163840   // 64 rows x 64 cap x 4B local candidate stacks
#define SM_RV     180224   // 64 x 26 f32 packed top-lists
#define SM_SQA    186880   // 64 f32
#define SM_SQB    187136   // 64 f32
#define SM_CIDB   187392   // 64 int
#define SM_THR    187648   // 64 f32 (packed, local rows)
#define SM_CN     187904   // 64 int
#define SM_CIDA   188160   // 64 int (cid of own rows)
#define SM_STAGE  188416   // 16KB tile staging [col][row] u32
#define SM_COLMIN 204800   // 2 x 64 f32 per-warp-half column minima
#define SMEM_BYTES 205312

// ---------------------------------------------------------------------------
// prep1: row sum-of-squares; argmax/max of categorical.
// ---------------------------------------------------------------------------
__global__ void prep_kernel(const float* __restrict__ enc,
                            const float* __restrict__ cat) {
    int warp = (blockIdx.x * blockDim.x + threadIdx.x) >> 5;
    int lane = threadIdx.x & 31;
    if (warp >= NB) return;

    const float* e = enc + (size_t)warp * ENCD;
    float s = 0.f;
#pragma unroll
    for (int i = 0; i < ENCD / 32; ++i) { float v = e[lane + 32 * i]; s += v * v; }
#pragma unroll
    for (int off = 16; off; off >>= 1) s += __shfl_xor_sync(0xffffffffu, s, off);

    float v = cat[(size_t)warp * NCL + lane];
    int idx = lane;
#pragma unroll
    for (int off = 16; off; off >>= 1) {
        float ov = __shfl_xor_sync(0xffffffffu, v, off);
        int   oi = __shfl_xor_sync(0xffffffffu, idx, off);
        if (ov > v || (ov == v && oi < idx)) { v = ov; idx = oi; }
    }
    if (lane == 0) { g_sq[warp] = s; g_maxp[warp] = v; g_cid[warp] = idx; }
}

// ---------------------------------------------------------------------------
// prep2: bf16 hi/lo split into pre-swizzled 32-row blobs.
// ---------------------------------------------------------------------------
__global__ void prep_b_kernel(const float* __restrict__ E) {
    int gid = blockIdx.x * blockDim.x + threadIdx.x;   // NB*32 threads
    int jb = gid >> 10;
    int r  = (gid >> 5) & 31;
    int c  = gid & 31;

    const float* src = E + (size_t)(jb * 32 + r) * ENCD + c * 8;
    float4 v0 = *(const float4*)src;
    float4 v1 = *(const float4*)(src + 4);
    float f[8] = {v0.x, v0.y, v0.z, v0.w, v1.x, v1.y, v1.z, v1.w};

    uint32_t hi[4], lo[4];
#pragma unroll
    for (int i = 0; i < 4; ++i) {
        __nv_bfloat16 h0 = __float2bfloat16(f[2 * i]);
        __nv_bfloat16 h1 = __float2bfloat16(f[2 * i + 1]);
        __nv_bfloat16 l0 = __float2bfloat16(f[2 * i] - __bfloat162float(h0));
        __nv_bfloat16 l1 = __float2bfloat16(f[2 * i + 1] - __bfloat162float(h1));
        __nv_bfloat162 hp; hp.x = h0; hp.y = h1;
        __nv_bfloat162 lp; lp.x = l0; lp.y = l1;
        hi[i] = *(uint32_t*)&hp;
        lo[i] = *(uint32_t*)&lp;
    }

    int base = jb * 8192;                                   // u32 units (32KB blob)
    int off  = (r * 512 + ((c ^ (r & 7)) << 4)) >> 2;       // u32 units
    *(uint4*)(g_Bblk + base + off)        = make_uint4(hi[0], hi[1], hi[2], hi[3]);
    *(uint4*)(g_Bblk + base + 4096 + off) = make_uint4(lo[0], lo[1], lo[2], lo[3]);
}

// ---------------------------------------------------------------------------
// Kernel A: 128 CTAs; CTA bi owns rows [bi*64, +64), tiles (bi,(bi+t)%128),
// t=0..64. bf16 3-term split, f32 acc (FROZEN numerics).
// Triple-buffered B ring, early prefetch. DEFERRED maintainer: tile t's
// maintainer + tile copy-out + smin store run in tile t+1's even chunk,
// overlapped with its MMAs (loop-top barrier provides all ordering).
// ---------------------------------------------------------------------------
__global__ void __launch_bounds__(NTHR, 1)
hmma_main() {
    extern __shared__ char smem[];
    const uint32_t sb = smem_to_u32(smem);
    const int tid  = threadIdx.x;
    const int lane = tid & 31;
    const int wid  = tid >> 5;
    const int mw   = wid & 1;        // 0/1 -> rows mw*32..+32
    const int nw   = wid >> 1;       // 0..3 -> cols nw*16..+16
    const int bi   = blockIdx.x;
    const int row0 = bi * BM;
    const int b2   = bi * 2;         // A blob pair

    float* s_sqa  = (float*)(smem + SM_SQA);
    float* s_sqb  = (float*)(smem + SM_SQB);
    int*   s_cidb = (int*)(smem + SM_CIDB);
    float* s_thr  = (float*)(smem + SM_THR);
    int*   s_cn   = (int*)(smem + SM_CN);
    int*   s_cida = (int*)(smem + SM_CIDA);
    uint32_t* s_cand  = (uint32_t*)(smem + SM_CAND);
    uint32_t* s_stage = (uint32_t*)(smem + SM_STAGE);
    float* s_colmin = (float*)(smem + SM_COLMIN);   // [2][64]
    float* s_rv   = (float*)(smem + SM_RV);

    // ---- prologue: A (64KB) + chunk0 (buf0) as group0; chunk1 (buf1) group1 ----
#pragma unroll
    for (int i = 0; i < 16; ++i) {
        int ck = tid + i * 256;                 // 0..4095 16B pieces
        int p  = ck >> 10;
        int off = ck & 1023;
        const uint32_t* src = g_Bblk + (size_t)(b2 + (p >> 1)) * 8192
                                     + (size_t)(p & 1) * 4096 + off * 4;
        cp16(sb + SM_A + (uint32_t)(p & 1) * 32768u + (uint32_t)(p >> 1) * 16384u + off * 16, src);
    }
#pragma unroll
    for (int i = 0; i < 8; ++i) {
        int ci = tid + i * 256;
        int hilo = ci >> 10, j = (ci >> 4) & 63, c = ci & 15;
        const uint32_t* src = g_Bblk + (size_t)(b2 + (j >> 5)) * 8192 + (size_t)hilo * 4096
                                     + (j & 31) * 128 + c * 4;
        cp16(sb + SM_B + hilo * 16384u + j * 256u + c * 16u, src);
    }
    cp_commit();   // group: A + chunk0
#pragma unroll
    for (int i = 0; i < 8; ++i) {
        int ci = tid + i * 256;
        int hilo = ci >> 10, j = (ci >> 4) & 63, c = ci & 15;
        const uint32_t* src = g_Bblk + (size_t)(b2 + (j >> 5)) * 8192 + (size_t)hilo * 4096
                                     + (j & 31) * 128 + 64 + c * 4;
        cp16(sb + SM_B + 32768u + hilo * 16384u + j * 256u + c * 16u, src);
    }
    cp_commit();   // group: chunk1

    if (tid < BM) {
        s_sqa[tid]  = g_sq[row0 + tid];
        s_cida[tid] = g_cid[row0 + tid];
        s_thr[tid]  = FLT_MAX;
        s_cn[tid]   = 0;
    }

    // ---- per-lane ldmatrix addressing ----
    const int lr = lane & 7, gq = lane >> 3;
    int a_row0 = mw * 32 + ((gq & 1) << 3) + lr;
    int a_row1 = a_row0 + 16;
    const uint32_t a_base0 = sb + SM_A + a_row0 * 512;
    const uint32_t a_base1 = sb + SM_A + a_row1 * 512;
    const int a_sw0 = a_row0 & 7, a_sw1 = a_row1 & 7;
    const int a_cb  = gq >> 1;
    const int j_l  = nw * 16 + ((gq >> 1) << 3) + lr;
    const int b_sw = j_l & 7;
    const int b_cb = gq & 1;
    const uint32_t b_roff = j_l * 256;

    int mcnt = 0;                 // maintainer count (tid<64 owns row tid)
    float acc[2][2][4];
    const int q  = lane >> 2;
    const int e0 = (lane & 3) * 2;

    int buf = 0;                  // buf index of chunk gc (mod-3 ring)
#pragma unroll 1
    for (int gc = 0; gc < NCHUNK; ++gc) {
        const int t = gc >> 1, h = gc & 1;
        const int bj = (bi + t) & (NBLK - 1);
        const uint32_t Bb = sb + SM_B + (uint32_t)buf * 32768u;

        cp_wait<1>();
        __syncthreads();   // chunk gc visible; orders pushes/stage/thr across tiles

        if (h == 0) {
#pragma unroll
            for (int ms = 0; ms < 2; ++ms)
#pragma unroll
                for (int ns = 0; ns < 2; ++ns)
#pragma unroll
                    for (int c = 0; c < 4; ++c) acc[ms][ns][c] = 0.f;
        } else if (tid < BN) {
            int j = bj * BN + tid;
            s_sqb[tid]  = g_sq[j];
            s_cidb[tid] = g_cid[j];
        }

        // ---- prefetch chunk gc+2 into the buffer freed at gc-1 ----
        {
            int pbuf = buf + 2; if (pbuf >= 3) pbuf -= 3;
            if (gc + 2 < NCHUNK) {
                const int t2 = (gc + 2) >> 1, h2 = (gc + 2) & 1;
                const int bj2 = (bi + t2) & (NBLK - 1);
                const uint32_t dstB = sb + SM_B + (uint32_t)pbuf * 32768u;
#pragma unroll
                for (int i = 0; i < 8; ++i) {
                    int ci = tid + i * 256;
                    int hilo = ci >> 10, j = (ci >> 4) & 63, c = ci & 15;
                    const uint32_t* src = g_Bblk + (size_t)(2 * bj2 + (j >> 5)) * 8192
                                                 + (size_t)hilo * 4096 + (j & 31) * 128
                                                 + h2 * 64 + c * 4;
                    cp16(dstB + hilo * 16384u + j * 256u + c * 16u, src);
                }
            }
            cp_commit();
        }

        // ---- deferred work for tile t-1 (overlaps this chunk's MMAs) ----
        if (h == 0 && t > 0) {
            const int tp  = t - 1;
            const int bjp = (bi + tp) & (NBLK - 1);
            const bool store_p = (tp != 0);   // tp<=63 here; tile-64 handled in tail
            if (store_p) {
                uint4* dst = (uint4*)(g_tile + (size_t)(bi * 64 + (tp - 1)) * 4096);
                const uint4* s4 = (const uint4*)s_stage;
#pragma unroll
                for (int i = 0; i < 4; ++i) dst[tid + i * 256] = s4[tid + i * 256];
            }
            if (tid < BM) {
                int n = s_cn[tid];
                float* rv = s_rv + tid * KEEP;
                for (int i = 0; i < n; ++i) {
                    float v = __uint_as_float(s_cand[tid * 64 + i]);
                    if (mcnt < KEEP) {
                        int p = mcnt++;
                        while (p > 0 && rv[p - 1] > v) { rv[p] = rv[p - 1]; --p; }
                        rv[p] = v;
                    } else if (v < rv[KEEP - 1]) {
                        int p = KEEP - 1;
                        while (p > 0 && rv[p - 1] > v) { rv[p] = rv[p - 1]; --p; }
                        rv[p] = v;
                    }
                }
                s_thr[tid] = (mcnt == KEEP) ? rv[KEEP - 1] : FLT_MAX;
                s_cn[tid] = 0;
                if (store_p) {
                    float mnn = fminf(s_colmin[tid], s_colmin[64 + tid]);
                    g_smin[(size_t)(bjp * 64 + tid) * 64 + (tp - 1)] = __float_as_uint(mnn);
                }
            }
        }

        // ---- compute chunk: 8 ksteps x (6 LDSM4 + 12 MMA) [FROZEN] ----
        const uint32_t aho = (uint32_t)h * 256u;
#pragma unroll
        for (int s = 0; s < 8; ++s) {
            const int kc = s * 2;
            uint32_t ah0[4], ah1[4], al0[4], al1[4], bh[4], bl[4];
            LDSM4(ah0[0], ah0[1], ah0[2], ah0[3], a_base0 + aho + (uint32_t)(((kc + a_cb) ^ a_sw0) << 4));
            LDSM4(ah1[0], ah1[1], ah1[2], ah1[3], a_base1 + aho + (uint32_t)(((kc + a_cb) ^ a_sw1) << 4));
            LDSM4(bh[0], bh[1], bh[2], bh[3], Bb + b_roff + (uint32_t)(((kc + b_cb) ^ b_sw) << 4));
            LDSM4(bl[0], bl[1], bl[2], bl[3], Bb + 16384u + b_roff + (uint32_t)(((kc + b_cb) ^ b_sw) << 4));
            LDSM4(al0[0], al0[1], al0[2], al0[3], a_base0 + 32768u + aho + (uint32_t)(((kc + a_cb) ^ a_sw0) << 4));
            LDSM4(al1[0], al1[1], al1[2], al1[3], a_base1 + 32768u + aho + (uint32_t)(((kc + a_cb) ^ a_sw1) << 4));

            MMA16816(acc[0][0], ah0[0], ah0[1], ah0[2], ah0[3], bh[0], bh[1]);  // hi*hi
            MMA16816(acc[0][1], ah0[0], ah0[1], ah0[2], ah0[3], bh[2], bh[3]);
            MMA16816(acc[1][0], ah1[0], ah1[1], ah1[2], ah1[3], bh[0], bh[1]);
            MMA16816(acc[1][1], ah1[0], ah1[1], ah1[2], ah1[3], bh[2], bh[3]);
            MMA16816(acc[0][0], ah0[0], ah0[1], ah0[2], ah0[3], bl[0], bl[1]);  // hi*lo
            MMA16816(acc[0][1], ah0[0], ah0[1], ah0[2], ah0[3], bl[2], bl[3]);
            MMA16816(acc[1][0], ah1[0], ah1[1], ah1[2], ah1[3], bl[0], bl[1]);
            MMA16816(acc[1][1], ah1[0], ah1[1], ah1[2], ah1[3], bl[2], bl[3]);
            MMA16816(acc[0][0], al0[0], al0[1], al0[2], al0[3], bh[0], bh[1]);  // lo*hi
            MMA16816(acc[0][1], al0[0], al0[1], al0[2], al0[3], bh[2], bh[3]);
            MMA16816(acc[1][0], al1[0], al1[1], al1[2], al1[3], bh[0], bh[1]);
            MMA16816(acc[1][1], al1[0], al1[1], al1[2], al1[3], bh[2], bh[3]);
        }

        if (h == 1) {
            const bool do_local = !(t == 64 && bi >= 64);
            if (do_local) {
                float cm[2][2] = {{FLT_MAX, FLT_MAX}, {FLT_MAX, FLT_MAX}};
                // ---- fused epilogue: local selection + stage tile + col mins ----
#pragma unroll
                for (int ms = 0; ms < 2; ++ms) {
#pragma unroll
                    for (int ro = 0; ro < 2; ++ro) {
                        const int row = mw * 32 + ms * 16 + ro * 8 + q;
                        const float sqa = s_sqa[row];
                        const float thr = s_thr[row];
                        const uint32_t cida = (uint32_t)s_cida[row];
#pragma unroll
                        for (int ns = 0; ns < 2; ++ns) {
#pragma unroll
                            for (int e = 0; e < 2; ++e) {
                                const int col = nw * 16 + ns * 8 + e0 + e;
                                float dot = acc[ms][ns][ro * 2 + e];
                                float d2 = fmaxf(sqa + s_sqb[col] - 2.f * dot, 0.f);
                                uint32_t bits = __float_as_uint(d2) & 0xFFFFFFE0u;
                                uint32_t pk = bits | (uint32_t)s_cidb[col];
                                if (__uint_as_float(pk) < thr) {
                                    int pos = atomicAdd(&s_cn[row], 1);
                                    s_cand[row * 64 + pos] = pk;
                                }
                                uint32_t sv = bits | cida;
                                s_stage[col * 64 + row] = sv;
                                cm[ns][e] = fminf(cm[ns][e], __uint_as_float(sv));
                            }
                        }
                    }
                }
                // reduce col mins across the 8 q-lanes (warp covers 32 rows)
#pragma unroll
                for (int ns = 0; ns < 2; ++ns)
#pragma unroll
                    for (int e = 0; e < 2; ++e) {
                        float m = cm[ns][e];
                        m = fminf(m, __shfl_xor_sync(0xffffffffu, m, 4));
                        m = fminf(m, __shfl_xor_sync(0xffffffffu, m, 8));
                        m = fminf(m, __shfl_xor_sync(0xffffffffu, m, 16));
                        if (lane < 4)
                            s_colmin[mw * 64 + nw * 16 + ns * 8 + lane * 2 + e] = m;
                    }
            }
            // no barrier, no maintainer here — deferred to next even chunk
        }

        if (++buf == 3) buf = 0;
    }

    // ---- tail: deferred work for tile 64 (real only for bi<64) ----
    __syncthreads();   // last epilogue's pushes/stage/colmin visible
    {
        const bool valid = (bi < 64);       // tile 64 epilogue ran only for bi<64
        const int bjp = (bi + 64) & (NBLK - 1);
        if (valid) {
            uint4* dst = (uint4*)(g_tile + (size_t)(bi * 64 + 63) * 4096);
            const uint4* s4 = (const uint4*)s_stage;
#pragma unroll
            for (int i = 0; i < 4; ++i) dst[tid + i * 256] = s4[tid + i * 256];
        }
        if (tid < BM) {
            int n = s_cn[tid];              // 0 when !valid (no pushes happened)
            float* rv = s_rv + tid * KEEP;
            for (int i = 0; i < n; ++i) {
                float v = __uint_as_float(s_cand[tid * 64 + i]);
                if (mcnt < KEEP) {
                    int p = mcnt++;
                    while (p > 0 && rv[p - 1] > v) { rv[p] = rv[p - 1]; --p; }
                    rv[p] = v;
                } else if (v < rv[KEEP - 1]) {
                    int p = KEEP - 1;
                    while (p > 0 && rv[p - 1] > v) { rv[p] = rv[p - 1]; --p; }
                    rv[p] = v;
                }
            }
            if (valid) {
                float mnn = fminf(s_colmin[tid], s_colmin[64 + tid]);
                g_smin[(size_t)(bjp * 64 + tid) * 64 + 63] = __float_as_uint(mnn);
            }
            // ---- write final local top-26 list ----
#pragma unroll
            for (int i = 0; i < KEEP; ++i)
                g_loc[(size_t)(row0 + tid) * KEEP + i] = __float_as_uint(rv[i]);
        }
    }
}

// ---------------------------------------------------------------------------
// Kernel B: one warp per row. Distributed sorted top-26 (lane L = rank L).
// Strip-minima mask, RE-FILTERED after every batch against the tightened
// threshold (lossless). Warp-parallel entropy via match_any.
// ---------------------------------------------------------------------------
__device__ __forceinline__ void dk_insert(float& mvd, float& thr, int lane, float val) {
    unsigned pb = __ballot_sync(0xffffffffu, mvd > val);
    int pos = __ffs(pb) - 1;
    float prev = __shfl_up_sync(0xffffffffu, mvd, 1);
    mvd = (lane > pos) ? prev : ((lane == pos) ? val : mvd);
    thr = __shfl_sync(0xffffffffu, mvd, KEEP - 1);
}

__device__ __forceinline__ void dk_pop(float& mvd, float& thr, int lane,
                                       float f, unsigned b) {
    while (b) {
        int sl = __ffs(b) - 1; b &= b - 1;
        float val = __shfl_sync(0xffffffffu, f, sl);
        if (val < thr) dk_insert(mvd, thr, lane, val);
    }
}

__global__ void __launch_bounds__(256)
gather_kernel(float* __restrict__ out) {
    const int w    = (blockIdx.x * blockDim.x + threadIdx.x) >> 5;   // row
    const int lane = threadIdx.x & 31;
    if (w >= NB) return;
    const int bj = w >> 6, cl = w & 63;

    float mvd = (lane < KEEP) ? __uint_as_float(g_loc[(size_t)w * KEEP + lane])
                              : FLT_MAX;
    float thr = __shfl_sync(0xffffffffu, mvd, KEEP - 1);

    const uint32_t* minb = g_smin + (size_t)w * 64;
    float m0 = __uint_as_float(__ldg(minb + lane));
    float m1 = __uint_as_float(__ldg(minb + lane + 32));
    unsigned b0 = __ballot_sync(0xffffffffu, m0 < thr);
    unsigned b1 = __ballot_sync(0xffffffffu, m1 < thr);
    unsigned long long mask = ((unsigned long long)b1 << 32) | (unsigned long long)b0;
    if (bj < 64) mask &= 0x7FFFFFFFFFFFFFFFull;   // p=63 invalid (never written)

    while (mask) {
        int pa[4]; uint2 v[4];
        int cnt = 0;
#pragma unroll
        for (int u = 0; u < 4; ++u) {
            if (mask) {
                pa[cnt] = __ffsll((long long)mask) - 1;
                mask &= mask - 1;
                ++cnt;
            }
        }
#pragma unroll
        for (int u = 0; u < 4; ++u) {
            if (u < cnt) {
                const int p = pa[u];
                const int bi = (bj - (p + 1)) & (NBLK - 1);
                v[u] = __ldg((const uint2*)(g_tile + (size_t)(bi * 64 + p) * 4096
                                            + cl * 64 + lane * 2));
            }
        }
#pragma unroll
        for (int u = 0; u < 4; ++u) {
            if (u < cnt) {
                float f0 = __uint_as_float(v[u].x), f1 = __uint_as_float(v[u].y);
                unsigned h0 = __ballot_sync(0xffffffffu, f0 < thr);
                unsigned h1 = __ballot_sync(0xffffffffu, f1 < thr);
                if (h0) dk_pop(mvd, thr, lane, f0, h0);
                if (h1) dk_pop(mvd, thr, lane, f1, h1);
            }
        }
        if (mask) {
            unsigned nb0 = __ballot_sync(0xffffffffu, m0 < thr);
            unsigned nb1 = __ballot_sync(0xffffffffu, m1 < thr);
            mask &= ((unsigned long long)nb1 << 32) | (unsigned long long)nb0;
        }
    }

    // ---- warp-parallel entropy over the distributed list ----
    float t25 = thr;
    unsigned below = __ballot_sync(0xffffffffu, mvd < t25) & ((1u << KSEL) - 1u);
    int n = __popc(below);
    float ent = 0.f;
    if (lane < n) {
        unsigned active = (1u << n) - 1u;
        int cidL = (int)(__float_as_uint(mvd) & 31u);
        unsigned peers = __match_any_sync(active, cidL);
        if (lane == (__ffs(peers) - 1)) {
            float bins = (float)__popc(peers) / (float)n;
            ent = -bins * logf(bins + 1e-5f);
        }
    }
#pragma unroll
    for (int off = 16; off; off >>= 1)
        ent += __shfl_xor_sync(0xffffffffu, ent, off);

    if (lane == 0) out[w] = ent * g_maxp[w];
}

// ---------------------------------------------------------------------------
extern "C" void kernel_launch(void* const* d_in, const int* in_sizes, int n_in,
                              void* d_out, int out_size) {
    const float* enc = (const float*)d_in[0];
    const float* cat = (const float*)d_in[1];
    float* out = (float*)d_out;

    cudaFuncSetAttribute(hmma_main,
                         cudaFuncAttributeMaxDynamicSharedMemorySize, SMEM_BYTES);

    prep_kernel<<<NB * 32 / NTHR, NTHR>>>(enc, cat);
    prep_b_kernel<<<NB * 32 / NTHR, NTHR>>>(enc);
    hmma_main<<<NBLK, NTHR, SMEM_BYTES>>>();
    gather_kernel<<<NB * 32 / 256, 256>>>(out);
}